// round 16
// baseline (speedup 1.0000x reference)
#include <cuda_runtime.h>
#include <cstdint>

#define BATCH   16
#define NPTS    4096
#define CIN     64
#define NPOINT  1024
#define NSAMPLE 32
#define R_TOTAL (BATCH*NPOINT*NSAMPLE)   // 524288 rows
#define NCENT   (BATCH*NPOINT)           // 16384
#define BN_EPS  1e-5f

typedef unsigned long long u64;

// ---------------- device scratch (no allocations allowed) ----------------
__device__ float g_new_xyz[BATCH*NPOINT*3];
__device__ int   g_gidx[BATCH*NPOINT*NSAMPLE];
__device__ float g_bufA[(size_t)64*R_TOTAL];    // 134 MB (layer0 out)
__device__ float g_bufB[(size_t)64*R_TOTAL];    // 134 MB (mlp1 out)
__device__ float g_pmax[(size_t)NCENT*128];     // 8 MB pooled (sign-flipped) max
__device__ float g_sumsL[3][256];               // per-layer: [0:128)=sum, [128:256)=sumsq

// ---------------- f32x2 helpers ----------------
__device__ __forceinline__ u64 pack2(float lo, float hi) {
    u64 r; asm("mov.b64 %0, {%1, %2};" : "=l"(r) : "f"(lo), "f"(hi)); return r;
}
__device__ __forceinline__ void unpack2(u64 v, float& lo, float& hi) {
    asm("mov.b64 {%0, %1}, %2;" : "=f"(lo), "=f"(hi) : "l"(v));
}
__device__ __forceinline__ void fma2(u64& d, u64 a, u64 b) {
    asm("fma.rn.f32x2 %0, %1, %2, %0;" : "+l"(d) : "l"(a), "l"(b));
}
__device__ __forceinline__ u64 add2_(u64 a, u64 b) {
    u64 r; asm("add.rn.f32x2 %0, %1, %2;" : "=l"(r) : "l"(a), "l"(b)); return r;
}
__device__ __forceinline__ u64 mul2_(u64 a, u64 b) {
    u64 r; asm("mul.rn.f32x2 %0, %1, %2;" : "=l"(r) : "l"(a), "l"(b)); return r;
}
__device__ __forceinline__ u64 umax64(u64 a, u64 b) { return a > b ? a : b; }

// BN scale/shift from accumulated sums
__device__ __forceinline__ void bn_coeffs(const float* sums, const float* gamma,
                                          const float* beta, int c,
                                          float& sc, float& sh)
{
    const float inv = 1.0f / (float)R_TOTAL;
    float mu  = sums[c] * inv;
    float var = sums[128 + c] * inv - mu*mu;
    sc = gamma[c] / sqrtf(var + BN_EPS);
    sh = fmaf(-mu, sc, beta[c]);
}

// ---------------- FPS: one block per batch, 256 thr, 16 pts/thr --------------
__global__ __launch_bounds__(256) void fps_kernel(const float* __restrict__ xyz,
                                                  float* __restrict__ d_out)
{
    const int b   = blockIdx.x;
    const int tid = threadIdx.x;
    const int lane = tid & 31, wid = tid >> 5;   // 8 warps
    const float* xb = xyz + (size_t)b*NPTS*3;

    if (b == 0 && tid < 256) {
        g_sumsL[0][tid] = 0.f; g_sumsL[1][tid] = 0.f; g_sumsL[2][tid] = 0.f;
    }

    u64 PX[8], PY[8], PZ[8];
    float dst[16];
#pragma unroll
    for (int q = 0; q < 8; q++) {
        int n0 = tid*16 + 2*q, n1 = n0 + 1;
        PX[q] = pack2(xb[n0*3+0], xb[n1*3+0]);
        PY[q] = pack2(xb[n0*3+1], xb[n1*3+1]);
        PZ[q] = pack2(xb[n0*3+2], xb[n1*3+2]);
    }
#pragma unroll
    for (int j = 0; j < 16; j++) dst[j] = 1e10f;

    __shared__ u64 s_k[2][8];    // parity double-buffer: (dist_bits<<32)|~idx

    float cx = xb[0], cy = xb[1], cz = xb[2];   // first center = point 0

    float* nxo = d_out     + (size_t)b*NPOINT*3;
    float* nxg = g_new_xyz + (size_t)b*NPOINT*3;

    for (int i = 0; i < NPOINT; i++) {
        if (tid == 0) {
            nxo[i*3+0] = cx; nxo[i*3+1] = cy; nxo[i*3+2] = cz;
            nxg[i*3+0] = cx; nxg[i*3+1] = cy; nxg[i*3+2] = cz;
        }
        const u64 vnx = pack2(-cx, -cx);
        const u64 vny = pack2(-cy, -cy);
        const u64 vnz = pack2(-cz, -cz);
#pragma unroll
        for (int q = 0; q < 8; q++) {
            u64 dx = add2_(PX[q], vnx);
            u64 dy = add2_(PY[q], vny);
            u64 dz = add2_(PZ[q], vnz);
            u64 d2 = add2_(add2_(mul2_(dx,dx), mul2_(dy,dy)), mul2_(dz,dz));
            float lo, hi; unpack2(d2, lo, hi);
            dst[2*q]   = fminf(dst[2*q],   lo);
            dst[2*q+1] = fminf(dst[2*q+1], hi);
        }
        float m01 = fmaxf(dst[0], dst[1]),  m23 = fmaxf(dst[2], dst[3]);
        float m45 = fmaxf(dst[4], dst[5]),  m67 = fmaxf(dst[6], dst[7]);
        float m89 = fmaxf(dst[8], dst[9]),  mAB = fmaxf(dst[10], dst[11]);
        float mCD = fmaxf(dst[12], dst[13]), mEF = fmaxf(dst[14], dst[15]);
        float mA = fmaxf(fmaxf(m01, m23), fmaxf(m45, m67));
        float mB = fmaxf(fmaxf(m89, mAB), fmaxf(mCD, mEF));
        float m  = fmaxf(mA, mB);
        unsigned msk = 0;
#pragma unroll
        for (int j = 0; j < 16; j++) msk |= (dst[j] == m) ? (1u << j) : 0u;
        int bj = __ffs(msk) - 1;
        int gidx = tid*16 + bj;

        unsigned mb   = __float_as_uint(m);
        unsigned wmax = __reduce_max_sync(0xffffffffu, mb);
        unsigned bal  = __ballot_sync(0xffffffffu, mb == wmax);
        int src  = __ffs(bal) - 1;
        int widx = __shfl_sync(0xffffffffu, gidx, src);
        if (lane == 0)
            s_k[i & 1][wid] = (((u64)wmax) << 32) | (unsigned)(~widx);
        __syncthreads();

        const ulonglong2* sp = (const ulonglong2*)s_k[i & 1];
        ulonglong2 a0 = sp[0], a1 = sp[1], a2 = sp[2], a3 = sp[3];
        u64 t0 = umax64(a0.x, a0.y), t1 = umax64(a1.x, a1.y);
        u64 t2 = umax64(a2.x, a2.y), t3 = umax64(a3.x, a3.y);
        u64 mm = umax64(umax64(t0, t1), umax64(t2, t3));
        int win = ~((int)(unsigned)(mm & 0xffffffffull));
        cx = xb[win*3+0]; cy = xb[win*3+1]; cz = xb[win*3+2];
    }
}

// ---------------- ball query: one warp per center ----------------
__global__ __launch_bounds__(128) void ballquery_kernel(const float* __restrict__ xyz)
{
    const int wg   = (blockIdx.x * blockDim.x + threadIdx.x) >> 5;  // center id
    const int lane = threadIdx.x & 31;
    if (wg >= NCENT) return;
    const int b = wg >> 10;
    const float* xb = xyz + (size_t)b*NPTS*3;

    const float cx = g_new_xyz[wg*3+0];
    const float cy = g_new_xyz[wg*3+1];
    const float cz = g_new_xyz[wg*3+2];
    const float sc = __fadd_rn(__fadd_rn(__fmul_rn(cx,cx), __fmul_rn(cy,cy)), __fmul_rn(cz,cz));
    const float TH = (float)(0.9*0.9);   // ref compares sqrt(d2) > radius**2 (!)

    int* gout = g_gidx + (size_t)wg*NSAMPLE;
    int cnt = 0;
    int first_idx = 0;
    bool have_first = false;

    for (int base = 0; base < NPTS; base += 32) {
        const int n = base + lane;
        float x = xb[n*3+0], y = xb[n*3+1], z = xb[n*3+2];
        float sp  = __fadd_rn(__fadd_rn(__fmul_rn(x,x), __fmul_rn(y,y)), __fmul_rn(z,z));
        float dot = __fadd_rn(__fadd_rn(__fmul_rn(cx,x), __fmul_rn(cy,y)), __fmul_rn(cz,z));
        float d2  = __fsub_rn(__fadd_rn(sc, sp), __fmul_rn(2.0f, dot));
        float dist = __fsqrt_rn(fmaxf(d2, 0.0f));
        bool in = !(dist > TH);
        unsigned bits = __ballot_sync(0xffffffffu, in);
        if (!have_first && bits) { first_idx = base + __ffs((int)bits) - 1; have_first = true; }
        if (in) {
            int pos = cnt + __popc(bits & ((1u << lane) - 1u));
            if (pos < NSAMPLE) gout[pos] = n;
        }
        cnt += __popc(bits);
        if (cnt >= NSAMPLE) break;
    }
    if (cnt < NSAMPLE) {
        for (int pos = cnt + lane; pos < NSAMPLE; pos += 32) gout[pos] = first_idx;
    }
}

// ---- stats epilogue (1 row/thread, oc-paired accs): packed butterflies -------
__device__ __forceinline__ void stats_epilogue1(const u64* acc, int lane, int ocb,
                                                float* sums)
{
    u64 ks = 0, kq = 0;
#pragma unroll
    for (int j = 0; j < 32; j++) {
        u64 s = acc[j];
        u64 q = mul2_(acc[j], acc[j]);
#pragma unroll
        for (int off = 16; off; off >>= 1) {
            s = add2_(s, __shfl_xor_sync(0xffffffffu, s, off));
            q = add2_(q, __shfl_xor_sync(0xffffffffu, q, off));
        }
        if (j == lane) { ks = s; kq = q; }
    }
    float slo, shi, qlo, qhi;
    unpack2(ks, slo, shi);
    unpack2(kq, qlo, qhi);
    const int ch = ocb + 2*lane;
    atomicAdd(&sums[ch],           slo);
    atomicAdd(&sums[ch + 1],       shi);
    atomicAdd(&sums[128 + ch],     qlo);
    atomicAdd(&sums[128 + ch + 1], qhi);
}

// ---------------- layer0: gather + concat + linear (IC=67, OC=64) -------------
// 1 row/thread, oc-paired weights (1 LDS.128 -> 2 fma2), 2 blocks/SM.
__global__ __launch_bounds__(256, 2) void layer0_kernel(const float* __restrict__ xyz,
                                                        const float* __restrict__ points,
                                                        const float* __restrict__ w,
                                                        const float* __restrict__ bias,
                                                        float* __restrict__ y)
{
    __shared__ u64   sw2[64*32];   // [c][j]: (w[2j][c+3], w[2j+1][c+3])
    __shared__ float sw3[3*64];
    __shared__ float sb[64];
    for (int i = threadIdx.x; i < 64*32; i += 256) {
        int c = i >> 5, j = i & 31;
        sw2[i] = pack2(w[(2*j)*67 + 3 + c], w[(2*j+1)*67 + 3 + c]);
    }
    if (threadIdx.x < 3*64) {
        int kk = threadIdx.x >> 6, oc = threadIdx.x & 63;
        sw3[threadIdx.x] = w[oc*67 + kk];
    }
    if (threadIdx.x < 64) sb[threadIdx.x] = bias[threadIdx.x];
    __syncthreads();

    const int r = blockIdx.x*256 + threadIdx.x;
    const int cen = r >> 5;
    const int bi = cen >> 10;
    const int n = g_gidx[r];
    const float4* qp = (const float4*)(points + ((size_t)(bi*NPTS + n))*CIN);
    const float x0 = xyz[(size_t)(bi*NPTS+n)*3+0] - g_new_xyz[cen*3+0];
    const float x1 = xyz[(size_t)(bi*NPTS+n)*3+1] - g_new_xyz[cen*3+1];
    const float x2 = xyz[(size_t)(bi*NPTS+n)*3+2] - g_new_xyz[cen*3+2];

    u64 acc[32];
#pragma unroll
    for (int j = 0; j < 32; j++) {
        float lo = sb[2*j],   hi = sb[2*j+1];
        lo = fmaf(sw3[2*j],     x0, lo); hi = fmaf(sw3[2*j+1],     x0, hi);
        lo = fmaf(sw3[64+2*j],  x1, lo); hi = fmaf(sw3[64+2*j+1],  x1, hi);
        lo = fmaf(sw3[128+2*j], x2, lo); hi = fmaf(sw3[128+2*j+1], x2, hi);
        acc[j] = pack2(lo, hi);
    }

    // prefetch ring depth 4 (4 outstanding LDG.128)
    float4 A[4];
#pragma unroll
    for (int k = 0; k < 4; k++) A[k] = qp[k];
#pragma unroll 1
    for (int cb = 0; cb < 16; cb++) {
        float4 a = A[cb & 3];
        if (cb + 4 < 16) A[cb & 3] = qp[cb + 4];
        const int c0 = cb*4;
        float va[4] = {a.x, a.y, a.z, a.w};
#pragma unroll
        for (int u = 0; u < 4; u++) {
            u64 xd = pack2(va[u], va[u]);
            const ulonglong2* wrow = (const ulonglong2*)(sw2 + (c0+u)*32);
#pragma unroll
            for (int q = 0; q < 16; q++) {
                ulonglong2 wv = wrow[q];
                fma2(acc[2*q],   wv.x, xd);
                fma2(acc[2*q+1], wv.y, xd);
            }
        }
    }
#pragma unroll
    for (int j = 0; j < 32; j++) {
        float lo, hi;
        unpack2(acc[j], lo, hi);
        y[(size_t)(2*j)*R_TOTAL   + r] = lo;
        y[(size_t)(2*j+1)*R_TOTAL + r] = hi;
    }
    stats_epilogue1(acc, threadIdx.x & 31, 0, g_sumsL[0]);
}

// ---------------- mlp1: BN(layer0)+relu input, linear 64->64, 1 row/thread ----
__global__ __launch_bounds__(256, 2) void mlp_layer_kernel(const float* __restrict__ x,
                                                           const float* __restrict__ w,
                                                           const float* __restrict__ bias,
                                                           const float* __restrict__ gamma,
                                                           const float* __restrict__ beta,
                                                           float* __restrict__ y)
{
    __shared__ u64   sw2[64*32];
    __shared__ float sb[64];
    __shared__ float ssc[64], ssh[64];
    for (int i = threadIdx.x; i < 64*32; i += 256) {
        int c = i >> 5, j = i & 31;
        sw2[i] = pack2(w[(2*j)*64 + c], w[(2*j+1)*64 + c]);
    }
    if (threadIdx.x < 64) {
        sb[threadIdx.x] = bias[threadIdx.x];
        float sc, sh;
        bn_coeffs(g_sumsL[0], gamma, beta, threadIdx.x, sc, sh);
        ssc[threadIdx.x] = sc; ssh[threadIdx.x] = sh;
    }
    __syncthreads();

    const int r = blockIdx.x*256 + threadIdx.x;
    const float* xr = x + r;

    u64 acc[32];
#pragma unroll
    for (int j = 0; j < 32; j++) acc[j] = pack2(sb[2*j], sb[2*j+1]);

    float buf[8];
#pragma unroll
    for (int k = 0; k < 8; k++) buf[k] = xr[(size_t)k*R_TOTAL];

#pragma unroll 1
    for (int cb = 0; cb < 64; cb += 8) {
#pragma unroll
        for (int u = 0; u < 8; u++) {
            const int c = cb + u;
            float v = buf[u];
            const int cp = c + 8;
            if (cp < 64) buf[u] = xr[(size_t)cp*R_TOTAL];
            float a = fmaxf(fmaf(v, ssc[c], ssh[c]), 0.0f);
            u64 xd = pack2(a, a);
            const ulonglong2* wrow = (const ulonglong2*)(sw2 + c*32);
#pragma unroll
            for (int q = 0; q < 16; q++) {
                ulonglong2 wv = wrow[q];
                fma2(acc[2*q],   wv.x, xd);
                fma2(acc[2*q+1], wv.y, xd);
            }
        }
    }
#pragma unroll
    for (int j = 0; j < 32; j++) {
        float lo, hi;
        unpack2(acc[j], lo, hi);
        y[(size_t)(2*j)*R_TOTAL   + r] = lo;
        y[(size_t)(2*j+1)*R_TOTAL + r] = hi;
    }
    stats_epilogue1(acc, threadIdx.x & 31, 0, g_sumsL[1]);
}

// ---------------- mlp2 fused: linear 64->128 (64 oc per blockIdx.y) + stats +
// per-center sign-flipped max pooling (warp == one center) ---------------------
__global__ __launch_bounds__(256, 2) void mlp2_pool_kernel(const float* __restrict__ x,
                                                           const float* __restrict__ w,
                                                           const float* __restrict__ bias,
                                                           const float* __restrict__ gamma,
                                                           const float* __restrict__ beta,
                                                           const float* __restrict__ gamma2)
{
    __shared__ u64   sw2[64*32];
    __shared__ float sb[64];
    __shared__ float ssc[64], ssh[64], sflip[64];
    const int ocb = blockIdx.y * 64;
    for (int i = threadIdx.x; i < 64*32; i += 256) {
        int c = i >> 5, j = i & 31;
        sw2[i] = pack2(w[(ocb + 2*j)*64 + c], w[(ocb + 2*j+1)*64 + c]);
    }
    if (threadIdx.x < 64) {
        sb[threadIdx.x] = bias[ocb + threadIdx.x];
        float sc, sh;
        bn_coeffs(g_sumsL[1], gamma, beta, threadIdx.x, sc, sh);
        ssc[threadIdx.x] = sc; ssh[threadIdx.x] = sh;
        sflip[threadIdx.x] = (gamma2[ocb + threadIdx.x] >= 0.0f) ? 1.0f : -1.0f;
    }
    __syncthreads();

    const int r = blockIdx.x*256 + threadIdx.x;
    const int lane = threadIdx.x & 31;
    const float* xr = x + r;

    u64 acc[32];
#pragma unroll
    for (int j = 0; j < 32; j++) acc[j] = pack2(sb[2*j], sb[2*j+1]);

    float buf[8];
#pragma unroll
    for (int k = 0; k < 8; k++) buf[k] = xr[(size_t)k*R_TOTAL];

#pragma unroll 1
    for (int cb = 0; cb < 64; cb += 8) {
#pragma unroll
        for (int u = 0; u < 8; u++) {
            const int c = cb + u;
            float v = buf[u];
            const int cp = c + 8;
            if (cp < 64) buf[u] = xr[(size_t)cp*R_TOTAL];
            float a = fmaxf(fmaf(v, ssc[c], ssh[c]), 0.0f);
            u64 xd = pack2(a, a);
            const ulonglong2* wrow = (const ulonglong2*)(sw2 + c*32);
#pragma unroll
            for (int q = 0; q < 16; q++) {
                ulonglong2 wv = wrow[q];
                fma2(acc[2*q],   wv.x, xd);
                fma2(acc[2*q+1], wv.y, xd);
            }
        }
    }

    // ---- pooling: this warp covers exactly center cen = r>>5 ----
    const int cen = r >> 5;
    float2* pout = (float2*)(g_pmax + (size_t)cen*128 + ocb);
#pragma unroll
    for (int j = 0; j < 32; j++) {
        u64 f2 = pack2(sflip[2*j], sflip[2*j+1]);
        u64 v = mul2_(acc[j], f2);
        float plo, phi;
        unpack2(v, plo, phi);
#pragma unroll
        for (int off = 16; off; off >>= 1) {
            plo = fmaxf(plo, __shfl_xor_sync(0xffffffffu, plo, off));
            phi = fmaxf(phi, __shfl_xor_sync(0xffffffffu, phi, off));
        }
        if (lane == j) pout[j] = make_float2(plo, phi);
    }
    stats_epilogue1(acc, lane, ocb, g_sumsL[2]);
}

// ---------------- final: BN coeffs from g_sumsL[2]; un-flip, BN + relu --------
__global__ __launch_bounds__(256) void final_kernel(const float* __restrict__ gamma,
                                                    const float* __restrict__ beta,
                                                    float* __restrict__ out)
{
    __shared__ float ssc[128], ssh[128], sflip[128];
    if (threadIdx.x < 128) {
        float sc, sh;
        bn_coeffs(g_sumsL[2], gamma, beta, threadIdx.x, sc, sh);
        ssc[threadIdx.x] = sc; ssh[threadIdx.x] = sh;
        sflip[threadIdx.x] = (gamma[threadIdx.x] >= 0.0f) ? 1.0f : -1.0f;
    }
    __syncthreads();

    const int idx = blockIdx.x*256 + threadIdx.x;     // NCENT*128
    const int ch = idx & 127;
    float v = sflip[ch] * g_pmax[idx];
    out[(size_t)BATCH*NPOINT*3 + idx] = fmaxf(fmaf(v, ssc[ch], ssh[ch]), 0.0f);
}

// ---------------- launcher ----------------
extern "C" void kernel_launch(void* const* d_in, const int* in_sizes, int n_in,
                              void* d_out, int out_size)
{
    (void)in_sizes; (void)n_in; (void)out_size;
    const float* xyz    = (const float*)d_in[0];
    const float* points = (const float*)d_in[1];
    const float* w0  = (const float*)d_in[2];
    const float* b0  = (const float*)d_in[3];
    const float* gm0 = (const float*)d_in[4];
    const float* bt0 = (const float*)d_in[5];
    const float* w1  = (const float*)d_in[6];
    const float* b1  = (const float*)d_in[7];
    const float* gm1 = (const float*)d_in[8];
    const float* bt1 = (const float*)d_in[9];
    const float* w2  = (const float*)d_in[10];
    const float* b2  = (const float*)d_in[11];
    const float* gm2 = (const float*)d_in[12];
    const float* bt2 = (const float*)d_in[13];
    float* out = (float*)d_out;

    float *bufA = nullptr, *bufB = nullptr;
    cudaGetSymbolAddress((void**)&bufA, g_bufA);
    cudaGetSymbolAddress((void**)&bufB, g_bufB);

    fps_kernel<<<BATCH, 256>>>(xyz, out);                                         // 1
    ballquery_kernel<<<NCENT/4, 128>>>(xyz);                                      // 2
    layer0_kernel<<<R_TOTAL/256, 256>>>(xyz, points, w0, b0, bufA);               // 3
    mlp_layer_kernel<<<R_TOTAL/256, 256>>>(bufA, w1, b1, gm0, bt0, bufB);         // 4 (profiled)
    mlp2_pool_kernel<<<dim3(R_TOTAL/256, 2), 256>>>(bufB, w2, b2, gm1, bt1, gm2); // 5
    final_kernel<<<(NCENT*128)/256, 256>>>(gm2, bt2, out);                        // 6
}

// round 17
// speedup vs baseline: 1.5538x; 1.5538x over previous
#include <cuda_runtime.h>
#include <cstdint>

#define BATCH   16
#define NPTS    4096
#define CIN     64
#define NPOINT  1024
#define NSAMPLE 32
#define R_TOTAL (BATCH*NPOINT*NSAMPLE)   // 524288 rows
#define NCENT   (BATCH*NPOINT)           // 16384
#define BN_EPS  1e-5f

typedef unsigned long long u64;

// ---------------- device scratch (no allocations allowed) ----------------
__device__ float g_new_xyz[BATCH*NPOINT*3];
__device__ int   g_gidx[BATCH*NPOINT*NSAMPLE];
__device__ float g_bufA[(size_t)64*R_TOTAL];    // 134 MB (layer0 out)
__device__ float g_bufB[(size_t)64*R_TOTAL];    // 134 MB (mlp1 out)
__device__ float g_pmax[(size_t)NCENT*128];     // 8 MB pooled (sign-flipped) max
__device__ float g_sumsL[3][256];               // per-layer: [0:128)=sum, [128:256)=sumsq

// ---------------- f32x2 helpers ----------------
__device__ __forceinline__ u64 pack2(float lo, float hi) {
    u64 r; asm("mov.b64 %0, {%1, %2};" : "=l"(r) : "f"(lo), "f"(hi)); return r;
}
__device__ __forceinline__ void unpack2(u64 v, float& lo, float& hi) {
    asm("mov.b64 {%0, %1}, %2;" : "=f"(lo), "=f"(hi) : "l"(v));
}
__device__ __forceinline__ void fma2(u64& d, u64 a, u64 b) {
    asm("fma.rn.f32x2 %0, %1, %2, %0;" : "+l"(d) : "l"(a), "l"(b));
}
__device__ __forceinline__ u64 add2_(u64 a, u64 b) {
    u64 r; asm("add.rn.f32x2 %0, %1, %2;" : "=l"(r) : "l"(a), "l"(b)); return r;
}
__device__ __forceinline__ u64 mul2_(u64 a, u64 b) {
    u64 r; asm("mul.rn.f32x2 %0, %1, %2;" : "=l"(r) : "l"(a), "l"(b)); return r;
}
__device__ __forceinline__ u64 umax64(u64 a, u64 b) { return a > b ? a : b; }

// BN scale/shift from accumulated sums
__device__ __forceinline__ void bn_coeffs(const float* sums, const float* gamma,
                                          const float* beta, int c,
                                          float& sc, float& sh)
{
    const float inv = 1.0f / (float)R_TOTAL;
    float mu  = sums[c] * inv;
    float var = sums[128 + c] * inv - mu*mu;
    sc = gamma[c] / sqrtf(var + BN_EPS);
    sh = fmaf(-mu, sc, beta[c]);
}

// ---------------- FPS: one block per batch, 256 thr, 16 pts/thr --------------
__global__ __launch_bounds__(256) void fps_kernel(const float* __restrict__ xyz,
                                                  float* __restrict__ d_out)
{
    const int b   = blockIdx.x;
    const int tid = threadIdx.x;
    const int lane = tid & 31, wid = tid >> 5;   // 8 warps
    const float* xb = xyz + (size_t)b*NPTS*3;

    if (b == 0 && tid < 256) {
        g_sumsL[0][tid] = 0.f; g_sumsL[1][tid] = 0.f; g_sumsL[2][tid] = 0.f;
    }

    u64 PX[8], PY[8], PZ[8];
    float dst[16];
#pragma unroll
    for (int q = 0; q < 8; q++) {
        int n0 = tid*16 + 2*q, n1 = n0 + 1;
        PX[q] = pack2(xb[n0*3+0], xb[n1*3+0]);
        PY[q] = pack2(xb[n0*3+1], xb[n1*3+1]);
        PZ[q] = pack2(xb[n0*3+2], xb[n1*3+2]);
    }
#pragma unroll
    for (int j = 0; j < 16; j++) dst[j] = 1e10f;

    __shared__ u64 s_k[2][8];    // parity double-buffer: (dist_bits<<32)|~idx

    float cx = xb[0], cy = xb[1], cz = xb[2];   // first center = point 0

    float* nxo = d_out     + (size_t)b*NPOINT*3;
    float* nxg = g_new_xyz + (size_t)b*NPOINT*3;

    for (int i = 0; i < NPOINT; i++) {
        if (tid == 0) {
            nxo[i*3+0] = cx; nxo[i*3+1] = cy; nxo[i*3+2] = cz;
            nxg[i*3+0] = cx; nxg[i*3+1] = cy; nxg[i*3+2] = cz;
        }
        const u64 vnx = pack2(-cx, -cx);
        const u64 vny = pack2(-cy, -cy);
        const u64 vnz = pack2(-cz, -cz);
#pragma unroll
        for (int q = 0; q < 8; q++) {
            u64 dx = add2_(PX[q], vnx);
            u64 dy = add2_(PY[q], vny);
            u64 dz = add2_(PZ[q], vnz);
            u64 d2 = add2_(add2_(mul2_(dx,dx), mul2_(dy,dy)), mul2_(dz,dz));
            float lo, hi; unpack2(d2, lo, hi);
            dst[2*q]   = fminf(dst[2*q],   lo);
            dst[2*q+1] = fminf(dst[2*q+1], hi);
        }
        float m01 = fmaxf(dst[0], dst[1]),  m23 = fmaxf(dst[2], dst[3]);
        float m45 = fmaxf(dst[4], dst[5]),  m67 = fmaxf(dst[6], dst[7]);
        float m89 = fmaxf(dst[8], dst[9]),  mAB = fmaxf(dst[10], dst[11]);
        float mCD = fmaxf(dst[12], dst[13]), mEF = fmaxf(dst[14], dst[15]);
        float mA = fmaxf(fmaxf(m01, m23), fmaxf(m45, m67));
        float mB = fmaxf(fmaxf(m89, mAB), fmaxf(mCD, mEF));
        float m  = fmaxf(mA, mB);
        unsigned msk = 0;
#pragma unroll
        for (int j = 0; j < 16; j++) msk |= (dst[j] == m) ? (1u << j) : 0u;
        int bj = __ffs(msk) - 1;
        int gidx = tid*16 + bj;

        unsigned mb   = __float_as_uint(m);
        unsigned wmax = __reduce_max_sync(0xffffffffu, mb);
        unsigned bal  = __ballot_sync(0xffffffffu, mb == wmax);
        int src  = __ffs(bal) - 1;
        int widx = __shfl_sync(0xffffffffu, gidx, src);
        if (lane == 0)
            s_k[i & 1][wid] = (((u64)wmax) << 32) | (unsigned)(~widx);
        __syncthreads();

        const ulonglong2* sp = (const ulonglong2*)s_k[i & 1];
        ulonglong2 a0 = sp[0], a1 = sp[1], a2 = sp[2], a3 = sp[3];
        u64 t0 = umax64(a0.x, a0.y), t1 = umax64(a1.x, a1.y);
        u64 t2 = umax64(a2.x, a2.y), t3 = umax64(a3.x, a3.y);
        u64 mm = umax64(umax64(t0, t1), umax64(t2, t3));
        int win = ~((int)(unsigned)(mm & 0xffffffffull));
        cx = xb[win*3+0]; cy = xb[win*3+1]; cz = xb[win*3+2];
    }
}

// ---------------- ball query: one warp per center ----------------
__global__ __launch_bounds__(128) void ballquery_kernel(const float* __restrict__ xyz)
{
    const int wg   = (blockIdx.x * blockDim.x + threadIdx.x) >> 5;  // center id
    const int lane = threadIdx.x & 31;
    if (wg >= NCENT) return;
    const int b = wg >> 10;
    const float* xb = xyz + (size_t)b*NPTS*3;

    const float cx = g_new_xyz[wg*3+0];
    const float cy = g_new_xyz[wg*3+1];
    const float cz = g_new_xyz[wg*3+2];
    const float sc = __fadd_rn(__fadd_rn(__fmul_rn(cx,cx), __fmul_rn(cy,cy)), __fmul_rn(cz,cz));
    const float TH = (float)(0.9*0.9);   // ref compares sqrt(d2) > radius**2 (!)

    int* gout = g_gidx + (size_t)wg*NSAMPLE;
    int cnt = 0;
    int first_idx = 0;
    bool have_first = false;

    for (int base = 0; base < NPTS; base += 32) {
        const int n = base + lane;
        float x = xb[n*3+0], y = xb[n*3+1], z = xb[n*3+2];
        float sp  = __fadd_rn(__fadd_rn(__fmul_rn(x,x), __fmul_rn(y,y)), __fmul_rn(z,z));
        float dot = __fadd_rn(__fadd_rn(__fmul_rn(cx,x), __fmul_rn(cy,y)), __fmul_rn(cz,z));
        float d2  = __fsub_rn(__fadd_rn(sc, sp), __fmul_rn(2.0f, dot));
        float dist = __fsqrt_rn(fmaxf(d2, 0.0f));
        bool in = !(dist > TH);
        unsigned bits = __ballot_sync(0xffffffffu, in);
        if (!have_first && bits) { first_idx = base + __ffs((int)bits) - 1; have_first = true; }
        if (in) {
            int pos = cnt + __popc(bits & ((1u << lane) - 1u));
            if (pos < NSAMPLE) gout[pos] = n;
        }
        cnt += __popc(bits);
        if (cnt >= NSAMPLE) break;
    }
    if (cnt < NSAMPLE) {
        for (int pos = cnt + lane; pos < NSAMPLE; pos += 32) gout[pos] = first_idx;
    }
}

// ---- stats epilogue: 2-row accs, 16 oc-pairs -> channels [ocb, ocb+32) -------
__device__ __forceinline__ void stats_epi16(const u64* a0, const u64* a1,
                                            int lane, int ocb, float* sums)
{
    u64 ks = 0, kq = 0;
#pragma unroll
    for (int j = 0; j < 16; j++) {
        u64 s = add2_(a0[j], a1[j]);
        u64 q = add2_(mul2_(a0[j], a0[j]), mul2_(a1[j], a1[j]));
#pragma unroll
        for (int off = 16; off; off >>= 1) {
            s = add2_(s, __shfl_xor_sync(0xffffffffu, s, off));
            q = add2_(q, __shfl_xor_sync(0xffffffffu, q, off));
        }
        if (j == lane) { ks = s; kq = q; }
    }
    if (lane < 16) {
        float slo, shi, qlo, qhi;
        unpack2(ks, slo, shi);
        unpack2(kq, qlo, qhi);
        const int ch = ocb + 2*lane;
        atomicAdd(&sums[ch],           slo);
        atomicAdd(&sums[ch + 1],       shi);
        atomicAdd(&sums[128 + ch],     qlo);
        atomicAdd(&sums[128 + ch + 1], qhi);
    }
}

// ---------------- layer0: gather + concat + linear (IC=67, OC=32/y-block) -----
// 2 rows/thread (r0=base+t, r1=r0+256), oc-paired weights, 2 blocks/SM.
__global__ __launch_bounds__(256, 2) void layer0_kernel(const float* __restrict__ xyz,
                                                        const float* __restrict__ points,
                                                        const float* __restrict__ w,
                                                        const float* __restrict__ bias,
                                                        float* __restrict__ y)
{
    __shared__ u64   sw2[64*16];   // [c][j]: (w[ocb+2j][c+3], w[ocb+2j+1][c+3])
    __shared__ float sw3[3*32];
    __shared__ float sb[32];
    const int ocb = blockIdx.y * 32;
    for (int i = threadIdx.x; i < 64*16; i += 256) {
        int c = i >> 4, j = i & 15;
        sw2[i] = pack2(w[(ocb+2*j)*67 + 3 + c], w[(ocb+2*j+1)*67 + 3 + c]);
    }
    if (threadIdx.x < 3*32) {
        int kk = threadIdx.x >> 5, oc = threadIdx.x & 31;
        sw3[threadIdx.x] = w[(ocb+oc)*67 + kk];
    }
    if (threadIdx.x < 32) sb[threadIdx.x] = bias[ocb + threadIdx.x];
    __syncthreads();

    const int base = blockIdx.x * 512;
    const int r0 = base + threadIdx.x;
    const int r1 = r0 + 256;
    const int cen0 = r0 >> 5, cen1 = r1 >> 5;
    const int b0i = cen0 >> 10, b1i = cen1 >> 10;
    const int n0 = g_gidx[r0];
    const int n1 = g_gidx[r1];
    const float4* q0 = (const float4*)(points + ((size_t)(b0i*NPTS + n0))*CIN);
    const float4* q1 = (const float4*)(points + ((size_t)(b1i*NPTS + n1))*CIN);
    const float x0a = xyz[(size_t)(b0i*NPTS+n0)*3+0] - g_new_xyz[cen0*3+0];
    const float x1a = xyz[(size_t)(b0i*NPTS+n0)*3+1] - g_new_xyz[cen0*3+1];
    const float x2a = xyz[(size_t)(b0i*NPTS+n0)*3+2] - g_new_xyz[cen0*3+2];
    const float x0b = xyz[(size_t)(b1i*NPTS+n1)*3+0] - g_new_xyz[cen1*3+0];
    const float x1b = xyz[(size_t)(b1i*NPTS+n1)*3+1] - g_new_xyz[cen1*3+1];
    const float x2b = xyz[(size_t)(b1i*NPTS+n1)*3+2] - g_new_xyz[cen1*3+2];

    u64 acc0[16], acc1[16];
#pragma unroll
    for (int j = 0; j < 16; j++) {
        float lo = sb[2*j],   hi = sb[2*j+1];
        lo = fmaf(sw3[2*j],    x0a, lo); hi = fmaf(sw3[2*j+1],    x0a, hi);
        lo = fmaf(sw3[32+2*j], x1a, lo); hi = fmaf(sw3[32+2*j+1], x1a, hi);
        lo = fmaf(sw3[64+2*j], x2a, lo); hi = fmaf(sw3[64+2*j+1], x2a, hi);
        acc0[j] = pack2(lo, hi);
        float l1 = sb[2*j],   h1 = sb[2*j+1];
        l1 = fmaf(sw3[2*j],    x0b, l1); h1 = fmaf(sw3[2*j+1],    x0b, h1);
        l1 = fmaf(sw3[32+2*j], x1b, l1); h1 = fmaf(sw3[32+2*j+1], x1b, h1);
        l1 = fmaf(sw3[64+2*j], x2b, l1); h1 = fmaf(sw3[64+2*j+1], x2b, h1);
        acc1[j] = pack2(l1, h1);
    }

    float4 A0 = q0[0], B0 = q1[0];
    float4 A1 = q0[1], B1 = q1[1];
#pragma unroll 1
    for (int cb = 0; cb < 16; cb++) {
        float4 a = A0, bb = B0;
        A0 = A1; B0 = B1;
        if (cb + 2 < 16) { A1 = q0[cb+2]; B1 = q1[cb+2]; }
        const int c0 = cb*4;
        float va[4] = {a.x, a.y, a.z, a.w};
        float vb[4] = {bb.x, bb.y, bb.z, bb.w};
#pragma unroll
        for (int u = 0; u < 4; u++) {
            u64 xd0 = pack2(va[u], va[u]);
            u64 xd1 = pack2(vb[u], vb[u]);
            const ulonglong2* wrow = (const ulonglong2*)(sw2 + (c0+u)*16);
#pragma unroll
            for (int q = 0; q < 8; q++) {
                ulonglong2 wv = wrow[q];
                fma2(acc0[2*q],   wv.x, xd0); fma2(acc0[2*q+1], wv.y, xd0);
                fma2(acc1[2*q],   wv.x, xd1); fma2(acc1[2*q+1], wv.y, xd1);
            }
        }
    }
#pragma unroll
    for (int j = 0; j < 16; j++) {
        float lo, hi;
        unpack2(acc0[j], lo, hi);
        y[(size_t)(ocb+2*j)*R_TOTAL   + r0] = lo;
        y[(size_t)(ocb+2*j+1)*R_TOTAL + r0] = hi;
        unpack2(acc1[j], lo, hi);
        y[(size_t)(ocb+2*j)*R_TOTAL   + r1] = lo;
        y[(size_t)(ocb+2*j+1)*R_TOTAL + r1] = hi;
    }
    stats_epi16(acc0, acc1, threadIdx.x & 31, ocb, g_sumsL[0]);
}

// ---------------- mlp1: BN(layer0)+relu input, linear 64->32/y-block ----------
__global__ __launch_bounds__(256, 2) void mlp_layer_kernel(const float* __restrict__ x,
                                                           const float* __restrict__ w,
                                                           const float* __restrict__ bias,
                                                           const float* __restrict__ gamma,
                                                           const float* __restrict__ beta,
                                                           float* __restrict__ y)
{
    __shared__ u64   sw2[64*16];
    __shared__ float sb[32];
    __shared__ float ssc[64], ssh[64];
    const int ocb = blockIdx.y * 32;
    for (int i = threadIdx.x; i < 64*16; i += 256) {
        int c = i >> 4, j = i & 15;
        sw2[i] = pack2(w[(ocb+2*j)*64 + c], w[(ocb+2*j+1)*64 + c]);
    }
    if (threadIdx.x < 64) {
        float sc, sh;
        bn_coeffs(g_sumsL[0], gamma, beta, threadIdx.x, sc, sh);
        ssc[threadIdx.x] = sc; ssh[threadIdx.x] = sh;
    }
    if (threadIdx.x < 32) sb[threadIdx.x] = bias[ocb + threadIdx.x];
    __syncthreads();

    const int r0 = blockIdx.x * 512 + threadIdx.x;
    const int r1 = r0 + 256;
    const float* xr0 = x + r0;
    const float* xr1 = x + r1;

    u64 acc0[16], acc1[16];
#pragma unroll
    for (int j = 0; j < 16; j++) {
        acc0[j] = pack2(sb[2*j], sb[2*j+1]);
        acc1[j] = acc0[j];
    }

    float b0[4], b1[4];
#pragma unroll
    for (int k = 0; k < 4; k++) {
        b0[k] = xr0[(size_t)k*R_TOTAL];
        b1[k] = xr1[(size_t)k*R_TOTAL];
    }

#pragma unroll 1
    for (int cb = 0; cb < 64; cb += 4) {
#pragma unroll
        for (int u = 0; u < 4; u++) {
            const int c = cb + u;
            float v0 = b0[u], v1 = b1[u];
            const int cp = c + 4;
            if (cp < 64) { b0[u] = xr0[(size_t)cp*R_TOTAL]; b1[u] = xr1[(size_t)cp*R_TOTAL]; }
            float s = ssc[c], h = ssh[c];
            float a0 = fmaxf(fmaf(v0, s, h), 0.0f);
            float a1 = fmaxf(fmaf(v1, s, h), 0.0f);
            u64 xd0 = pack2(a0, a0);
            u64 xd1 = pack2(a1, a1);
            const ulonglong2* wrow = (const ulonglong2*)(sw2 + c*16);
#pragma unroll
            for (int q = 0; q < 8; q++) {
                ulonglong2 wv = wrow[q];
                fma2(acc0[2*q],   wv.x, xd0); fma2(acc0[2*q+1], wv.y, xd0);
                fma2(acc1[2*q],   wv.x, xd1); fma2(acc1[2*q+1], wv.y, xd1);
            }
        }
    }
#pragma unroll
    for (int j = 0; j < 16; j++) {
        float lo, hi;
        unpack2(acc0[j], lo, hi);
        y[(size_t)(ocb+2*j)*R_TOTAL   + r0] = lo;
        y[(size_t)(ocb+2*j+1)*R_TOTAL + r0] = hi;
        unpack2(acc1[j], lo, hi);
        y[(size_t)(ocb+2*j)*R_TOTAL   + r1] = lo;
        y[(size_t)(ocb+2*j+1)*R_TOTAL + r1] = hi;
    }
    stats_epi16(acc0, acc1, threadIdx.x & 31, ocb, g_sumsL[1]);
}

// ---------------- mlp2 fused: linear 64->32/y-block (4 y-blocks) + stats +
// per-center sign-flipped max pooling ------------------------------------------
__global__ __launch_bounds__(256, 2) void mlp2_pool_kernel(const float* __restrict__ x,
                                                           const float* __restrict__ w,
                                                           const float* __restrict__ bias,
                                                           const float* __restrict__ gamma,
                                                           const float* __restrict__ beta,
                                                           const float* __restrict__ gamma2)
{
    __shared__ u64   sw2[64*16];
    __shared__ float sb[32];
    __shared__ float ssc[64], ssh[64];
    __shared__ float sflip[32];
    const int ocb = blockIdx.y * 32;
    for (int i = threadIdx.x; i < 64*16; i += 256) {
        int c = i >> 4, j = i & 15;
        sw2[i] = pack2(w[(ocb+2*j)*64 + c], w[(ocb+2*j+1)*64 + c]);
    }
    if (threadIdx.x < 64) {
        float sc, sh;
        bn_coeffs(g_sumsL[1], gamma, beta, threadIdx.x, sc, sh);
        ssc[threadIdx.x] = sc; ssh[threadIdx.x] = sh;
    }
    if (threadIdx.x < 32) {
        sb[threadIdx.x] = bias[ocb + threadIdx.x];
        sflip[threadIdx.x] = (gamma2[ocb + threadIdx.x] >= 0.0f) ? 1.0f : -1.0f;
    }
    __syncthreads();

    const int base = blockIdx.x * 512;
    const int r0 = base + threadIdx.x;
    const int r1 = r0 + 256;
    const int lane = threadIdx.x & 31, wid = threadIdx.x >> 5;
    const float* xr0 = x + r0;
    const float* xr1 = x + r1;

    u64 acc0[16], acc1[16];
#pragma unroll
    for (int j = 0; j < 16; j++) {
        acc0[j] = pack2(sb[2*j], sb[2*j+1]);
        acc1[j] = acc0[j];
    }

    float b0[4], b1[4];
#pragma unroll
    for (int k = 0; k < 4; k++) {
        b0[k] = xr0[(size_t)k*R_TOTAL];
        b1[k] = xr1[(size_t)k*R_TOTAL];
    }

#pragma unroll 1
    for (int cb = 0; cb < 64; cb += 4) {
#pragma unroll
        for (int u = 0; u < 4; u++) {
            const int c = cb + u;
            float v0 = b0[u], v1 = b1[u];
            const int cp = c + 4;
            if (cp < 64) { b0[u] = xr0[(size_t)cp*R_TOTAL]; b1[u] = xr1[(size_t)cp*R_TOTAL]; }
            float s = ssc[c], h = ssh[c];
            float a0 = fmaxf(fmaf(v0, s, h), 0.0f);
            float a1 = fmaxf(fmaf(v1, s, h), 0.0f);
            u64 xd0 = pack2(a0, a0);
            u64 xd1 = pack2(a1, a1);
            const ulonglong2* wrow = (const ulonglong2*)(sw2 + c*16);
#pragma unroll
            for (int q = 0; q < 8; q++) {
                ulonglong2 wv = wrow[q];
                fma2(acc0[2*q],   wv.x, xd0); fma2(acc0[2*q+1], wv.y, xd0);
                fma2(acc1[2*q],   wv.x, xd1); fma2(acc1[2*q+1], wv.y, xd1);
            }
        }
    }

    // ---- pooling: acc0 rows -> center cen0=(base>>5)+wid, acc1 -> cen0+8 ----
    const int cen0 = (base >> 5) + wid;
    const int cen1 = cen0 + 8;
#pragma unroll
    for (int j = 0; j < 16; j++) {
        u64 f2 = pack2(sflip[2*j], sflip[2*j+1]);
        u64 v0 = mul2_(acc0[j], f2);
        u64 v1 = mul2_(acc1[j], f2);
        float p00, p01, p10, p11;
        unpack2(v0, p00, p01);
        unpack2(v1, p10, p11);
#pragma unroll
        for (int off = 16; off; off >>= 1) {
            p00 = fmaxf(p00, __shfl_xor_sync(0xffffffffu, p00, off));
            p01 = fmaxf(p01, __shfl_xor_sync(0xffffffffu, p01, off));
            p10 = fmaxf(p10, __shfl_xor_sync(0xffffffffu, p10, off));
            p11 = fmaxf(p11, __shfl_xor_sync(0xffffffffu, p11, off));
        }
        if (lane == j) {
            ((float2*)(g_pmax + (size_t)cen0*128 + ocb))[j] = make_float2(p00, p01);
            ((float2*)(g_pmax + (size_t)cen1*128 + ocb))[j] = make_float2(p10, p11);
        }
    }
    stats_epi16(acc0, acc1, lane, ocb, g_sumsL[2]);
}

// ---------------- final: BN coeffs from g_sumsL[2]; un-flip, BN + relu --------
__global__ __launch_bounds__(256) void final_kernel(const float* __restrict__ gamma,
                                                    const float* __restrict__ beta,
                                                    float* __restrict__ out)
{
    __shared__ float ssc[128], ssh[128], sflip[128];
    if (threadIdx.x < 128) {
        float sc, sh;
        bn_coeffs(g_sumsL[2], gamma, beta, threadIdx.x, sc, sh);
        ssc[threadIdx.x] = sc; ssh[threadIdx.x] = sh;
        sflip[threadIdx.x] = (gamma[threadIdx.x] >= 0.0f) ? 1.0f : -1.0f;
    }
    __syncthreads();

    const int idx = blockIdx.x*256 + threadIdx.x;     // NCENT*128
    const int ch = idx & 127;
    float v = sflip[ch] * g_pmax[idx];
    out[(size_t)BATCH*NPOINT*3 + idx] = fmaxf(fmaf(v, ssc[ch], ssh[ch]), 0.0f);
}

// ---------------- launcher ----------------
extern "C" void kernel_launch(void* const* d_in, const int* in_sizes, int n_in,
                              void* d_out, int out_size)
{
    (void)in_sizes; (void)n_in; (void)out_size;
    const float* xyz    = (const float*)d_in[0];
    const float* points = (const float*)d_in[1];
    const float* w0  = (const float*)d_in[2];
    const float* b0  = (const float*)d_in[3];
    const float* gm0 = (const float*)d_in[4];
    const float* bt0 = (const float*)d_in[5];
    const float* w1  = (const float*)d_in[6];
    const float* b1  = (const float*)d_in[7];
    const float* gm1 = (const float*)d_in[8];
    const float* bt1 = (const float*)d_in[9];
    const float* w2  = (const float*)d_in[10];
    const float* b2  = (const float*)d_in[11];
    const float* gm2 = (const float*)d_in[12];
    const float* bt2 = (const float*)d_in[13];
    float* out = (float*)d_out;

    float *bufA = nullptr, *bufB = nullptr;
    cudaGetSymbolAddress((void**)&bufA, g_bufA);
    cudaGetSymbolAddress((void**)&bufB, g_bufB);

    fps_kernel<<<BATCH, 256>>>(xyz, out);                                         // 1
    ballquery_kernel<<<NCENT/4, 128>>>(xyz);                                      // 2
    layer0_kernel<<<dim3(R_TOTAL/512, 2), 256>>>(xyz, points, w0, b0, bufA);      // 3
    mlp_layer_kernel<<<dim3(R_TOTAL/512, 2), 256>>>(bufA, w1, b1, gm0, bt0, bufB);// 4 (profiled)
    mlp2_pool_kernel<<<dim3(R_TOTAL/512, 4), 256>>>(bufB, w2, b2, gm1, bt1, gm2); // 5
    final_kernel<<<(NCENT*128)/256, 256>>>(gm2, bt2, out);                        // 6
}